// round 2
// baseline (speedup 1.0000x reference)
#include <cuda_runtime.h>

#define S_LEN 2048
#define B_SZ 2
#define DM 1024
#define NH 16
#define DK 64
#define ROWS (B_SZ * S_LEN)   // 4096

// Scratch (allocation-free): projected Q, K, V and attention context.
__device__ float g_Q[(size_t)ROWS * DM];
__device__ float g_K[(size_t)ROWS * DM];
__device__ float g_V[(size_t)ROWS * DM];
__device__ float g_C[(size_t)ROWS * DM];

// ---------------------------------------------------------------------------
// GEMM with fused bias:  C[m][n] = sum_k A[m][k] * W[n][k] + bias[n]
// (torch Linear convention: x @ W.T + b; both A and W are K-contiguous)
// 64x64 block tile, BK=16, 256 threads, 4x4 per-thread microtile.
// M, N, K are multiples of 64/16 here (4096, 1024, 1024) — no bounds checks.
// ---------------------------------------------------------------------------
__global__ __launch_bounds__(256) void gemm_bias(
    const float* __restrict__ A, const float* __restrict__ W,
    const float* __restrict__ bias, float* __restrict__ C,
    int M, int N, int K)
{
    __shared__ float As[16][65];   // [BK][BM+1] (transposed stage, padded)
    __shared__ float Ws[16][65];

    const int tid = threadIdx.x;
    const int tx = tid & 15;       // 0..15 -> 4 output cols each
    const int ty = tid >> 4;       // 0..15 -> 4 output rows each
    const int row0 = blockIdx.y * 64;
    const int col0 = blockIdx.x * 64;
    const int lk = tid & 15;       // k within tile for loading
    const int lr = tid >> 4;       // row group for loading

    float acc[4][4] = {};

    for (int k0 = 0; k0 < K; k0 += 16) {
        #pragma unroll
        for (int i = 0; i < 4; i++) {
            const int m = lr + i * 16;
            As[lk][m] = A[(size_t)(row0 + m) * K + k0 + lk];
            Ws[lk][m] = W[(size_t)(col0 + m) * K + k0 + lk];
        }
        __syncthreads();

        #pragma unroll
        for (int kk = 0; kk < 16; kk++) {
            float ra[4], rb[4];
            #pragma unroll
            for (int i = 0; i < 4; i++) ra[i] = As[kk][ty * 4 + i];
            #pragma unroll
            for (int j = 0; j < 4; j++) rb[j] = Ws[kk][tx * 4 + j];
            #pragma unroll
            for (int i = 0; i < 4; i++)
                #pragma unroll
                for (int j = 0; j < 4; j++)
                    acc[i][j] = fmaf(ra[i], rb[j], acc[i][j]);
        }
        __syncthreads();
    }

    #pragma unroll
    for (int i = 0; i < 4; i++) {
        const int m = row0 + ty * 4 + i;
        #pragma unroll
        for (int j = 0; j < 4; j++) {
            const int n = col0 + tx * 4 + j;
            C[(size_t)m * N + n] = acc[i][j] + bias[n];
        }
    }
}

// ---------------------------------------------------------------------------
// Flash attention, fp32. One CTA = 64 queries x one head. Streams 64-key
// tiles with online softmax. Shared memory is double-dutied per tile:
//   buf1: Q tile (scores phase)  ->  P tile (PV phase)
//   buf2: K tile (scores phase)  ->  V tile (PV phase)
// Q is re-read from L2 every key tile (16 KB; stays L2-hot) to keep static
// smem at 2 * 64*65*4 = 33.3 KB -> high occupancy, no func-attr calls.
// Thread layout: 16x16; thread (ty,tx) owns queries 4ty..+3.
//   scores phase: keys 4tx..+3;  PV phase: output dims 4tx..+3.
// Row softmax stats reduced across the 16 tx lanes via shfl_xor (each
// 16-lane group is one half-warp: tid>>4 == ty, so lanes share ty).
// ---------------------------------------------------------------------------
__global__ __launch_bounds__(256) void flash_attn(
    const float* __restrict__ Qm, const float* __restrict__ Km,
    const float* __restrict__ Vm, float* __restrict__ Om)
{
    __shared__ float b1[64 * 65];  // Q, then P
    __shared__ float b2[64 * 65];  // K, then V

    const int tid = threadIdx.x;
    const int tx = tid & 15;
    const int ty = tid >> 4;
    const int h  = blockIdx.y;
    const int b  = blockIdx.z;
    const int q0 = blockIdx.x * 64;
    const size_t base = (size_t)b * S_LEN * DM + h * DK;
    const float scale = 0.125f;    // 1/sqrt(64)

    float m_i[4], l_i[4], acc[4][4];
    #pragma unroll
    for (int i = 0; i < 4; i++) {
        m_i[i] = -1e30f; l_i[i] = 0.0f;
        #pragma unroll
        for (int j = 0; j < 4; j++) acc[i][j] = 0.0f;
    }

    for (int k0 = 0; k0 < S_LEN; k0 += 64) {
        // Stage Q tile (b1) and K tile (b2).
        for (int i = tid; i < 64 * 64; i += 256) {
            const int r = i >> 6, c = i & 63;
            b1[r * 65 + c] = Qm[base + (size_t)(q0 + r) * DM + c];
            b2[r * 65 + c] = Km[base + (size_t)(k0 + r) * DM + c];
        }
        __syncthreads();

        // s[4][4] = Q(4ty..) . K(4tx..)
        float s[4][4] = {};
        #pragma unroll 8
        for (int d = 0; d < 64; d++) {
            float ra[4], rb[4];
            #pragma unroll
            for (int i = 0; i < 4; i++) ra[i] = b1[(ty * 4 + i) * 65 + d];
            #pragma unroll
            for (int j = 0; j < 4; j++) rb[j] = b2[(tx * 4 + j) * 65 + d];
            #pragma unroll
            for (int i = 0; i < 4; i++)
                #pragma unroll
                for (int j = 0; j < 4; j++)
                    s[i][j] = fmaf(ra[i], rb[j], s[i][j]);
        }
        __syncthreads();  // everyone done reading Q/K tiles

        // Stage V tile into b2 (overwrites K — reads finished above).
        for (int i = tid; i < 64 * 64; i += 256) {
            const int r = i >> 6, c = i & 63;
            b2[r * 65 + c] = Vm[base + (size_t)(k0 + r) * DM + c];
        }

        // Online softmax update; write probabilities P into b1.
        #pragma unroll
        for (int i = 0; i < 4; i++) {
            float mx = -1e30f;
            #pragma unroll
            for (int j = 0; j < 4; j++) {
                s[i][j] *= scale;
                mx = fmaxf(mx, s[i][j]);
            }
            #pragma unroll
            for (int off = 8; off >= 1; off >>= 1)
                mx = fmaxf(mx, __shfl_xor_sync(0xffffffffu, mx, off));
            const float mn = fmaxf(m_i[i], mx);
            float ps = 0.0f;
            #pragma unroll
            for (int j = 0; j < 4; j++) {
                s[i][j] = __expf(s[i][j] - mn);
                ps += s[i][j];
            }
            #pragma unroll
            for (int off = 8; off >= 1; off >>= 1)
                ps += __shfl_xor_sync(0xffffffffu, ps, off);
            const float f = __expf(m_i[i] - mn);
            l_i[i] = l_i[i] * f + ps;
            m_i[i] = mn;
            #pragma unroll
            for (int j = 0; j < 4; j++) acc[i][j] *= f;
            #pragma unroll
            for (int j = 0; j < 4; j++)
                b1[(ty * 4 + i) * 65 + tx * 4 + j] = s[i][j];
        }
        __syncthreads();  // P and V visible

        // acc += P(64q x 64k) @ V(64k x 64d); thread owns dims 4tx..+3 now.
        #pragma unroll 8
        for (int k = 0; k < 64; k++) {
            float rp[4], rv[4];
            #pragma unroll
            for (int i = 0; i < 4; i++) rp[i] = b1[(ty * 4 + i) * 65 + k];
            #pragma unroll
            for (int j = 0; j < 4; j++) rv[j] = b2[k * 65 + tx * 4 + j];
            #pragma unroll
            for (int i = 0; i < 4; i++)
                #pragma unroll
                for (int j = 0; j < 4; j++)
                    acc[i][j] = fmaf(rp[i], rv[j], acc[i][j]);
        }
        __syncthreads();  // before next tile overwrites b1/b2
    }

    // Normalize and write context (already in [B,S, h*64+d] layout).
    #pragma unroll
    for (int i = 0; i < 4; i++) {
        const float inv = 1.0f / l_i[i];
        const size_t rowp = base + (size_t)(q0 + ty * 4 + i) * DM;
        #pragma unroll
        for (int j = 0; j < 4; j++)
            Om[rowp + tx * 4 + j] = acc[i][j] * inv;
    }
}

// ---------------------------------------------------------------------------
// Launch: 3 projection GEMMs -> flash attention -> output GEMM.
// All launches only; scratch in __device__ globals; capture-safe.
// ---------------------------------------------------------------------------
extern "C" void kernel_launch(void* const* d_in, const int* in_sizes, int n_in,
                              void* d_out, int out_size)
{
    const float* q  = (const float*)d_in[0];
    const float* k  = (const float*)d_in[1];
    const float* v  = (const float*)d_in[2];
    const float* Wq = (const float*)d_in[3];
    const float* bq = (const float*)d_in[4];
    const float* Wk = (const float*)d_in[5];
    const float* bk = (const float*)d_in[6];
    const float* Wv = (const float*)d_in[7];
    const float* bv = (const float*)d_in[8];
    const float* Wo = (const float*)d_in[9];
    const float* bo = (const float*)d_in[10];
    float* out = (float*)d_out;

    float *gq, *gk, *gv, *gc;
    cudaGetSymbolAddress((void**)&gq, g_Q);
    cudaGetSymbolAddress((void**)&gk, g_K);
    cudaGetSymbolAddress((void**)&gv, g_V);
    cudaGetSymbolAddress((void**)&gc, g_C);

    dim3 blk(256);
    dim3 gproj(DM / 64, ROWS / 64);      // (16, 64)
    gemm_bias<<<gproj, blk>>>(q, Wq, bq, gq, ROWS, DM, DM);
    gemm_bias<<<gproj, blk>>>(k, Wk, bk, gk, ROWS, DM, DM);
    gemm_bias<<<gproj, blk>>>(v, Wv, bv, gv, ROWS, DM, DM);

    dim3 gfl(S_LEN / 64, NH, B_SZ);      // (32, 16, 2)
    flash_attn<<<gfl, blk>>>(gq, gk, gv, gc);

    gemm_bias<<<gproj, blk>>>(gc, Wo, bo, out, ROWS, DM, DM);
}

// round 3
// speedup vs baseline: 9.3563x; 9.3563x over previous
#include <cuda_runtime.h>
#include <cuda_fp16.h>
#include <cstdint>

#define S_LEN 2048
#define B_SZ 2
#define DM 1024
#define NH 16
#define DK 64
#define ROWS (B_SZ * S_LEN)   // 4096

// ---------------------------------------------------------------------------
// Scratch (allocation-free __device__ globals)
// fp16 copies of inputs/weights + fp16 intermediates.
// ---------------------------------------------------------------------------
__device__ __align__(16) __half g_qh[(size_t)ROWS * DM];
__device__ __align__(16) __half g_kh[(size_t)ROWS * DM];
__device__ __align__(16) __half g_vh[(size_t)ROWS * DM];
__device__ __align__(16) __half g_Wqh[(size_t)DM * DM];
__device__ __align__(16) __half g_Wkh[(size_t)DM * DM];
__device__ __align__(16) __half g_Wvh[(size_t)DM * DM];
__device__ __align__(16) __half g_Woh[(size_t)DM * DM];
__device__ __align__(16) __half g_Qh[(size_t)ROWS * DM];
__device__ __align__(16) __half g_Kh[(size_t)ROWS * DM];
__device__ __align__(16) __half g_Vh[(size_t)ROWS * DM];
__device__ __align__(16) __half g_Ch[(size_t)ROWS * DM];

// ---------------------------------------------------------------------------
// PTX helpers
// ---------------------------------------------------------------------------
__device__ __forceinline__ uint32_t sptr(const void* p) {
    return (uint32_t)__cvta_generic_to_shared(p);
}
__device__ __forceinline__ void ldm_x4(uint32_t& r0, uint32_t& r1,
                                       uint32_t& r2, uint32_t& r3, uint32_t a) {
    asm volatile("ldmatrix.sync.aligned.m8n8.x4.shared.b16 {%0,%1,%2,%3},[%4];\n"
                 : "=r"(r0), "=r"(r1), "=r"(r2), "=r"(r3) : "r"(a));
}
__device__ __forceinline__ void ldm_x4_t(uint32_t& r0, uint32_t& r1,
                                         uint32_t& r2, uint32_t& r3, uint32_t a) {
    asm volatile("ldmatrix.sync.aligned.m8n8.x4.trans.shared.b16 {%0,%1,%2,%3},[%4];\n"
                 : "=r"(r0), "=r"(r1), "=r"(r2), "=r"(r3) : "r"(a));
}
__device__ __forceinline__ void mma16816(float* c, const uint32_t* a,
                                         uint32_t b0, uint32_t b1) {
    asm volatile(
        "mma.sync.aligned.m16n8k16.row.col.f32.f16.f16.f32 "
        "{%0,%1,%2,%3},{%4,%5,%6,%7},{%8,%9},{%0,%1,%2,%3};\n"
        : "+f"(c[0]), "+f"(c[1]), "+f"(c[2]), "+f"(c[3])
        : "r"(a[0]), "r"(a[1]), "r"(a[2]), "r"(a[3]), "r"(b0), "r"(b1));
}
__device__ __forceinline__ uint32_t pack_h2(float x, float y) {
    __half2 h = __floats2half2_rn(x, y);
    return *reinterpret_cast<uint32_t*>(&h);
}

// ---------------------------------------------------------------------------
// fp32 -> fp16 conversion (vectorized)
// ---------------------------------------------------------------------------
__global__ void f2h(const float4* __restrict__ in, __half2* __restrict__ out, int n4) {
    int i = blockIdx.x * blockDim.x + threadIdx.x;
    if (i < n4) {
        float4 v = in[i];
        out[2 * i]     = __floats2half2_rn(v.x, v.y);
        out[2 * i + 1] = __floats2half2_rn(v.z, v.w);
    }
}

// ---------------------------------------------------------------------------
// HMMA GEMM with fused bias: C[m][n] = sum_k A[m][k]*W[n][k] + bias[n]
// A: [M,K] fp16 (K-contig).  W: [N,K] fp16 (K-contig) -> B col-major frags via
// non-trans ldmatrix.  CTA tile 128x128, BK=64, 8 warps as 2(m) x 4(n),
// warp tile 64x32, m16n8k16 microtiles, fp32 accumulation.
// ---------------------------------------------------------------------------
template <bool HALF_OUT>
__global__ __launch_bounds__(256) void gemm_bias_tc(
    const __half* __restrict__ A, const __half* __restrict__ W,
    const float* __restrict__ bias, void* __restrict__ Cout,
    int M, int N, int K)
{
    __shared__ __half As[128 * 72];   // row stride 72 halfs (144B, 16B-mult)
    __shared__ __half Ws[128 * 72];

    const int tid = threadIdx.x;
    const int warp = tid >> 5, lane = tid & 31;
    const int wm = warp >> 2;          // 0..1 -> m offset 64*wm
    const int wn = warp & 3;           // 0..3 -> n offset 32*wn
    const int row0 = blockIdx.y * 128;
    const int col0 = blockIdx.x * 128;

    float acc[4][4][4];                // [mtile][ntile][4]
    #pragma unroll
    for (int i = 0; i < 4; i++)
        #pragma unroll
        for (int j = 0; j < 4; j++)
            #pragma unroll
            for (int r = 0; r < 4; r++) acc[i][j][r] = 0.0f;

    const int srow = tid >> 3;          // 0..31
    const int scol = (tid & 7) * 8;     // 0..56

    for (int k0 = 0; k0 < K; k0 += 64) {
        #pragma unroll
        for (int i = 0; i < 4; i++) {
            const int r = srow + i * 32;
            *(uint4*)&As[r * 72 + scol] =
                *(const uint4*)&A[(size_t)(row0 + r) * K + k0 + scol];
            *(uint4*)&Ws[r * 72 + scol] =
                *(const uint4*)&W[(size_t)(col0 + r) * K + k0 + scol];
        }
        __syncthreads();

        #pragma unroll
        for (int kk = 0; kk < 64; kk += 16) {
            uint32_t af[4][4];
            #pragma unroll
            for (int mt = 0; mt < 4; mt++) {
                const int r = wm * 64 + mt * 16 + (lane & 15);
                const int c = kk + ((lane >> 4) << 3);
                ldm_x4(af[mt][0], af[mt][1], af[mt][2], af[mt][3],
                       sptr(&As[r * 72 + c]));
            }
            uint32_t bf[4][2];
            #pragma unroll
            for (int nt = 0; nt < 4; nt += 2) {
                const int g = lane >> 3;
                const int rr = wn * 32 + nt * 8 + ((g >= 2) ? 8 : 0) + (lane & 7);
                const int cc = kk + ((g & 1) << 3);
                ldm_x4(bf[nt][0], bf[nt][1], bf[nt + 1][0], bf[nt + 1][1],
                       sptr(&Ws[rr * 72 + cc]));
            }
            #pragma unroll
            for (int mt = 0; mt < 4; mt++)
                #pragma unroll
                for (int nt = 0; nt < 4; nt++)
                    mma16816(acc[mt][nt], af[mt], bf[nt][0], bf[nt][1]);
        }
        __syncthreads();
    }

    // Epilogue: c0=(r,c) c1=(r,c+1) c2=(r+8,c) c3=(r+8,c+1)
    #pragma unroll
    for (int mt = 0; mt < 4; mt++) {
        const int r = row0 + wm * 64 + mt * 16 + (lane >> 2);
        #pragma unroll
        for (int nt = 0; nt < 4; nt++) {
            const int c = col0 + wn * 32 + nt * 8 + ((lane & 3) << 1);
            const float b0 = bias[c], b1 = bias[c + 1];
            if (HALF_OUT) {
                __half* C = (__half*)Cout;
                *(__half2*)&C[(size_t)r * N + c] =
                    __floats2half2_rn(acc[mt][nt][0] + b0, acc[mt][nt][1] + b1);
                *(__half2*)&C[(size_t)(r + 8) * N + c] =
                    __floats2half2_rn(acc[mt][nt][2] + b0, acc[mt][nt][3] + b1);
            } else {
                float* C = (float*)Cout;
                float2 v0 = {acc[mt][nt][0] + b0, acc[mt][nt][1] + b1};
                float2 v1 = {acc[mt][nt][2] + b0, acc[mt][nt][3] + b1};
                *(float2*)&C[(size_t)r * N + c] = v0;
                *(float2*)&C[(size_t)(r + 8) * N + c] = v1;
            }
        }
    }
}

// ---------------------------------------------------------------------------
// Flash attention, HMMA (FA2-style register pipeline).
// CTA = 64 queries x 1 head (4 warps x 16 queries). 64-key tiles.
// Scores: Q-frags (hoisted) x K-frags (non-trans ldmatrix, d-contig rows).
// Softmax: fp32 in registers, quad shfl reductions (rows split 4 lanes).
// PV: P converted in-register to A-frags; V-frags via ldmatrix.trans.
// ---------------------------------------------------------------------------
__global__ __launch_bounds__(128) void flash_attn_tc(
    const __half* __restrict__ Qm, const __half* __restrict__ Km,
    const __half* __restrict__ Vm, __half* __restrict__ Om)
{
    __shared__ __half Qs[64 * 72];
    __shared__ __half Ks[64 * 72];
    __shared__ __half Vs[64 * 72];

    const int tid = threadIdx.x;
    const int warp = tid >> 5, lane = tid & 31;
    const int h = blockIdx.y, b = blockIdx.z;
    const int q0 = blockIdx.x * 64;
    const size_t base = (size_t)b * S_LEN * DM + (size_t)h * DK;
    const float scale = 0.125f;  // 1/sqrt(64)

    // Stage Q tile, hoist Q A-frags (4 k-steps of 16).
    const int srow = tid >> 3;          // 0..15
    const int scol = (tid & 7) * 8;
    #pragma unroll
    for (int i = 0; i < 4; i++) {
        const int r = srow + i * 16;
        *(uint4*)&Qs[r * 72 + scol] =
            *(const uint4*)&Qm[base + (size_t)(q0 + r) * DM + scol];
    }
    __syncthreads();
    uint32_t qf[4][4];
    #pragma unroll
    for (int ks = 0; ks < 4; ks++) {
        const int r = warp * 16 + (lane & 15);
        const int c = ks * 16 + ((lane >> 4) << 3);
        ldm_x4(qf[ks][0], qf[ks][1], qf[ks][2], qf[ks][3], sptr(&Qs[r * 72 + c]));
    }

    float m_[2] = {-1e30f, -1e30f};
    float l_[2] = {0.0f, 0.0f};
    float o[8][4];
    #pragma unroll
    for (int nt = 0; nt < 8; nt++)
        #pragma unroll
        for (int r = 0; r < 4; r++) o[nt][r] = 0.0f;

    for (int k0 = 0; k0 < S_LEN; k0 += 64) {
        __syncthreads();   // prior iter's Ks/Vs reads done before overwrite
        #pragma unroll
        for (int i = 0; i < 4; i++) {
            const int r = srow + i * 16;
            *(uint4*)&Ks[r * 72 + scol] =
                *(const uint4*)&Km[base + (size_t)(k0 + r) * DM + scol];
            *(uint4*)&Vs[r * 72 + scol] =
                *(const uint4*)&Vm[base + (size_t)(k0 + r) * DM + scol];
        }
        __syncthreads();

        // ---- scores S = Q . K^T  (8 key n-tiles) ----
        float s[8][4];
        #pragma unroll
        for (int nt = 0; nt < 8; nt++)
            #pragma unroll
            for (int r = 0; r < 4; r++) s[nt][r] = 0.0f;

        #pragma unroll
        for (int ks = 0; ks < 4; ks++) {
            #pragma unroll
            for (int nt = 0; nt < 8; nt += 2) {
                uint32_t b0, b1, b2, b3;
                const int g = lane >> 3;
                const int rr = nt * 8 + ((g >= 2) ? 8 : 0) + (lane & 7);
                const int cc = ks * 16 + ((g & 1) << 3);
                ldm_x4(b0, b1, b2, b3, sptr(&Ks[rr * 72 + cc]));
                mma16816(s[nt], qf[ks], b0, b1);
                mma16816(s[nt + 1], qf[ks], b2, b3);
            }
        }

        // ---- online softmax (rows r=lane>>2 and r+8; cols across lane&3) ----
        float mx0 = -1e30f, mx1 = -1e30f;
        #pragma unroll
        for (int nt = 0; nt < 8; nt++) {
            s[nt][0] *= scale; s[nt][1] *= scale;
            s[nt][2] *= scale; s[nt][3] *= scale;
            mx0 = fmaxf(mx0, fmaxf(s[nt][0], s[nt][1]));
            mx1 = fmaxf(mx1, fmaxf(s[nt][2], s[nt][3]));
        }
        #pragma unroll
        for (int off = 1; off <= 2; off <<= 1) {
            mx0 = fmaxf(mx0, __shfl_xor_sync(0xffffffffu, mx0, off));
            mx1 = fmaxf(mx1, __shfl_xor_sync(0xffffffffu, mx1, off));
        }
        const float mn0 = fmaxf(m_[0], mx0);
        const float mn1 = fmaxf(m_[1], mx1);
        const float f0 = __expf(m_[0] - mn0);
        const float f1 = __expf(m_[1] - mn1);
        float sum0 = 0.0f, sum1 = 0.0f;
        #pragma unroll
        for (int nt = 0; nt < 8; nt++) {
            s[nt][0] = __expf(s[nt][0] - mn0); sum0 += s[nt][0];
            s[nt][1] = __expf(s[nt][1] - mn0); sum0 += s[nt][1];
            s[nt][2] = __expf(s[nt][2] - mn1); sum1 += s[nt][2];
            s[nt][3] = __expf(s[nt][3] - mn1); sum1 += s[nt][3];
        }
        #pragma unroll
        for (int off = 1; off <= 2; off <<= 1) {
            sum0 += __shfl_xor_sync(0xffffffffu, sum0, off);
            sum1 += __shfl_xor_sync(0xffffffffu, sum1, off);
        }
        l_[0] = l_[0] * f0 + sum0;
        l_[1] = l_[1] * f1 + sum1;
        m_[0] = mn0; m_[1] = mn1;
        #pragma unroll
        for (int nt = 0; nt < 8; nt++) {
            o[nt][0] *= f0; o[nt][1] *= f0;
            o[nt][2] *= f1; o[nt][3] *= f1;
        }

        // ---- O += P @ V  (P in-register as A-frags; V via trans ldmatrix) ----
        #pragma unroll
        for (int kt = 0; kt < 4; kt++) {
            uint32_t pa[4];
            pa[0] = pack_h2(s[2 * kt][0],     s[2 * kt][1]);
            pa[1] = pack_h2(s[2 * kt][2],     s[2 * kt][3]);
            pa[2] = pack_h2(s[2 * kt + 1][0], s[2 * kt + 1][1]);
            pa[3] = pack_h2(s[2 * kt + 1][2], s[2 * kt + 1][3]);
            #pragma unroll
            for (int nt = 0; nt < 8; nt += 2) {
                uint32_t b0, b1, b2, b3;
                const int g = lane >> 3;
                const int rr = kt * 16 + ((g & 1) << 3) + (lane & 7);
                const int cc = nt * 8 + ((g >= 2) ? 8 : 0);
                ldm_x4_t(b0, b1, b2, b3, sptr(&Vs[rr * 72 + cc]));
                mma16816(o[nt], pa, b0, b1);
                mma16816(o[nt + 1], pa, b2, b3);
            }
        }
    }

    // ---- epilogue: normalize, write context (fp16) ----
    const float inv0 = 1.0f / l_[0];
    const float inv1 = 1.0f / l_[1];
    const int r = q0 + warp * 16 + (lane >> 2);
    #pragma unroll
    for (int nt = 0; nt < 8; nt++) {
        const int c = nt * 8 + ((lane & 3) << 1);
        *(__half2*)&Om[base + (size_t)r * DM + c] =
            __floats2half2_rn(o[nt][0] * inv0, o[nt][1] * inv0);
        *(__half2*)&Om[base + (size_t)(r + 8) * DM + c] =
            __floats2half2_rn(o[nt][2] * inv1, o[nt][3] * inv1);
    }
}

// ---------------------------------------------------------------------------
// Launch pipeline (capture-safe, allocation-free).
// ---------------------------------------------------------------------------
extern "C" void kernel_launch(void* const* d_in, const int* in_sizes, int n_in,
                              void* d_out, int out_size)
{
    const float* q  = (const float*)d_in[0];
    const float* k  = (const float*)d_in[1];
    const float* v  = (const float*)d_in[2];
    const float* Wq = (const float*)d_in[3];
    const float* bq = (const float*)d_in[4];
    const float* Wk = (const float*)d_in[5];
    const float* bk = (const float*)d_in[6];
    const float* Wv = (const float*)d_in[7];
    const float* bv = (const float*)d_in[8];
    const float* Wo = (const float*)d_in[9];
    const float* bo = (const float*)d_in[10];
    float* out = (float*)d_out;

    __half *qh, *kh, *vh, *Wqh, *Wkh, *Wvh, *Woh, *Qh, *Kh, *Vh, *Ch;
    cudaGetSymbolAddress((void**)&qh,  g_qh);
    cudaGetSymbolAddress((void**)&kh,  g_kh);
    cudaGetSymbolAddress((void**)&vh,  g_vh);
    cudaGetSymbolAddress((void**)&Wqh, g_Wqh);
    cudaGetSymbolAddress((void**)&Wkh, g_Wkh);
    cudaGetSymbolAddress((void**)&Wvh, g_Wvh);
    cudaGetSymbolAddress((void**)&Woh, g_Woh);
    cudaGetSymbolAddress((void**)&Qh,  g_Qh);
    cudaGetSymbolAddress((void**)&Kh,  g_Kh);
    cudaGetSymbolAddress((void**)&Vh,  g_Vh);
    cudaGetSymbolAddress((void**)&Ch,  g_Ch);

    const int nAct4 = ROWS * DM / 4;   // 1,048,576
    const int nW4   = DM * DM / 4;     //   262,144
    f2h<<<(nAct4 + 255) / 256, 256>>>((const float4*)q,  (__half2*)qh,  nAct4);
    f2h<<<(nAct4 + 255) / 256, 256>>>((const float4*)k,  (__half2*)kh,  nAct4);
    f2h<<<(nAct4 + 255) / 256, 256>>>((const float4*)v,  (__half2*)vh,  nAct4);
    f2h<<<(nW4 + 255) / 256, 256>>>((const float4*)Wq, (__half2*)Wqh, nW4);
    f2h<<<(nW4 + 255) / 256, 256>>>((const float4*)Wk, (__half2*)Wkh, nW4);
    f2h<<<(nW4 + 255) / 256, 256>>>((const float4*)Wv, (__half2*)Wvh, nW4);
    f2h<<<(nW4 + 255) / 256, 256>>>((const float4*)Wo, (__half2*)Woh, nW4);

    dim3 blk(256);
    dim3 gproj(DM / 128, ROWS / 128);   // (8, 32)
    gemm_bias_tc<true><<<gproj, blk>>>(qh, Wqh, bq, Qh, ROWS, DM, DM);
    gemm_bias_tc<true><<<gproj, blk>>>(kh, Wkh, bk, Kh, ROWS, DM, DM);
    gemm_bias_tc<true><<<gproj, blk>>>(vh, Wvh, bv, Vh, ROWS, DM, DM);

    dim3 gfl(S_LEN / 64, NH, B_SZ);     // (32, 16, 2)
    flash_attn_tc<<<gfl, dim3(128)>>>(Qh, Kh, Vh, Ch);

    gemm_bias_tc<false><<<gproj, blk>>>(Ch, Woh, bo, out, ROWS, DM, DM);
}